// round 2
// baseline (speedup 1.0000x reference)
#include <cuda_runtime.h>
#include <cstdint>

#define D128 128
#define MAXN 50000

// ---------------- scratch (no cudaMalloc allowed) ----------------
__device__ float g_H[MAXN * D128];    // GEMM output (reused both layers)
__device__ float g_O1[MAXN * D128];   // layer-1 aggregated output
__device__ int   g_deg[MAXN];
__device__ float g_dinv[MAXN];
__device__ float g_sum[D128];
__device__ float g_sumsq[D128];
__device__ float g_scale[D128];
__device__ float g_bias[D128];

// ---------------- init: deg=1 (self loop), zero BN sums ----------------
__global__ void k_init(int N) {
    int i = blockIdx.x * blockDim.x + threadIdx.x;
    if (i < N) g_deg[i] = 1;
    if (i < D128) { g_sum[i] = 0.f; g_sumsq[i] = 0.f; }
}

// ---------------- degree accumulation over dst ----------------
__global__ void k_deg(const int* __restrict__ dst, int E) {
    int e = blockIdx.x * blockDim.x + threadIdx.x;
    if (e < E) atomicAdd(&g_deg[dst[e]], 1);
}

__global__ void k_dinv(int N) {
    int i = blockIdx.x * blockDim.x + threadIdx.x;
    if (i < N) g_dinv[i] = rsqrtf((float)g_deg[i]);
}

// ---------------- GEMM: Out[N,128] = act(A)[N,128] @ W[128,128] ----------------
// 64 rows x 128 cols per block, 256 threads, each thread 8 rows x 4 cols.
// Optional fused BN-affine+ReLU on the input (scl/bia non-null).
__global__ __launch_bounds__(256) void k_gemm(
    const float* __restrict__ A, const float* __restrict__ W,
    float* __restrict__ Out, int N,
    const float* __restrict__ scl, const float* __restrict__ bia)
{
    __shared__ float xs[64 * D128];
    const int tid = threadIdx.x;
    const int brow = blockIdx.x * 64;

    // load 64x128 tile (coalesced float4), optional BN+ReLU
    #pragma unroll
    for (int i = 0; i < 8; i++) {
        int fid = i * 256 + tid;        // float4 index, 2048 total
        int row = fid >> 5;
        int c4  = fid & 31;
        int grow = brow + row;
        float4 v = make_float4(0.f, 0.f, 0.f, 0.f);
        if (grow < N)
            v = ((const float4*)(A + (size_t)grow * D128))[c4];
        if (scl != nullptr) {
            int f = c4 * 4;
            v.x = fmaxf(fmaf(v.x, scl[f + 0], bia[f + 0]), 0.f);
            v.y = fmaxf(fmaf(v.y, scl[f + 1], bia[f + 1]), 0.f);
            v.z = fmaxf(fmaf(v.z, scl[f + 2], bia[f + 2]), 0.f);
            v.w = fmaxf(fmaf(v.w, scl[f + 3], bia[f + 3]), 0.f);
        }
        ((float4*)xs)[fid] = v;
    }
    __syncthreads();

    const int cg = tid & 31;   // column group: cols 4*cg..4*cg+3
    const int rg = tid >> 5;   // row group: rows 8*rg..8*rg+7
    float acc[8][4];
    #pragma unroll
    for (int r = 0; r < 8; r++)
        #pragma unroll
        for (int c = 0; c < 4; c++) acc[r][c] = 0.f;

    const float4* Wv = (const float4*)W;
    #pragma unroll 4
    for (int k = 0; k < D128; k++) {
        float4 b = Wv[k * 32 + cg];          // coalesced, L1-resident
        #pragma unroll
        for (int r = 0; r < 8; r++) {
            float a = xs[(rg * 8 + r) * D128 + k];   // warp-broadcast LDS
            acc[r][0] = fmaf(a, b.x, acc[r][0]);
            acc[r][1] = fmaf(a, b.y, acc[r][1]);
            acc[r][2] = fmaf(a, b.z, acc[r][2]);
            acc[r][3] = fmaf(a, b.w, acc[r][3]);
        }
    }

    #pragma unroll
    for (int r = 0; r < 8; r++) {
        int grow = brow + rg * 8 + r;
        if (grow < N)
            ((float4*)(Out + (size_t)grow * D128))[cg] =
                make_float4(acc[r][0], acc[r][1], acc[r][2], acc[r][3]);
    }
}

// ---------------- O[i] = b + H[i] * dinv[i]^2  (self-loop + bias) ----------------
__global__ void k_selfinit(const float* __restrict__ H, const float* __restrict__ b,
                           float* __restrict__ O, int N)
{
    int idx = blockIdx.x * blockDim.x + threadIdx.x;   // float4 index
    int total = N * 32;
    if (idx >= total) return;
    int row = idx >> 5;
    int c4  = idx & 31;
    float di = g_dinv[row];
    float w = di * di;
    float4 h = ((const float4*)H)[idx];
    float4 bb = ((const float4*)b)[c4];
    float4 o;
    o.x = fmaf(h.x, w, bb.x);
    o.y = fmaf(h.y, w, bb.y);
    o.z = fmaf(h.z, w, bb.z);
    o.w = fmaf(h.w, w, bb.w);
    ((float4*)O)[idx] = o;
}

// ---------------- edge scatter: O[dst] += H[src] * dinv[src]*dinv[dst] ----------------
__device__ __forceinline__ void red_add_v4(float* p, float a, float b, float c, float d) {
    asm volatile("red.global.add.v4.f32 [%0], {%1,%2,%3,%4};"
                 :: "l"(p), "f"(a), "f"(b), "f"(c), "f"(d) : "memory");
}

__global__ __launch_bounds__(256) void k_scatter(
    const float* __restrict__ H, float* __restrict__ O,
    const int* __restrict__ src, const int* __restrict__ dst, int E)
{
    int warp = (blockIdx.x * blockDim.x + threadIdx.x) >> 5;
    int lane = threadIdx.x & 31;
    if (warp >= E) return;
    int s = src[warp];
    int d = dst[warp];
    float nrm = g_dinv[s] * g_dinv[d];
    float4 v = ((const float4*)(H + (size_t)s * D128))[lane];
    float* p = O + (size_t)d * D128 + lane * 4;
    red_add_v4(p, v.x * nrm, v.y * nrm, v.z * nrm, v.w * nrm);
}

// ---------------- BatchNorm reduce ----------------
__global__ __launch_bounds__(256) void k_bnreduce(const float* __restrict__ H, int N) {
    int f    = threadIdx.x & 127;
    int half = threadIdx.x >> 7;     // 0/1
    float s = 0.f, s2 = 0.f;
    for (int row = blockIdx.x * 2 + half; row < N; row += gridDim.x * 2) {
        float v = H[(size_t)row * D128 + f];
        s += v;
        s2 = fmaf(v, v, s2);
    }
    __shared__ float sh[256], sh2[256];
    sh[threadIdx.x] = s; sh2[threadIdx.x] = s2;
    __syncthreads();
    if (threadIdx.x < 128) {
        atomicAdd(&g_sum[f],   sh[f] + sh[f + 128]);
        atomicAdd(&g_sumsq[f], sh2[f] + sh2[f + 128]);
    }
}

__global__ void k_bnfinal(const float* __restrict__ gamma, const float* __restrict__ beta, int N) {
    int f = threadIdx.x;
    if (f >= D128) return;
    float inv_n = 1.0f / (float)N;
    float mu  = g_sum[f] * inv_n;
    float var = g_sumsq[f] * inv_n - mu * mu;
    float rstd = rsqrtf(var + 1e-5f);
    float s = rstd * gamma[f];
    g_scale[f] = s;
    g_bias[f]  = beta[f] - mu * s;
}

// ---------------- launch ----------------
extern "C" void kernel_launch(void* const* d_in, const int* in_sizes, int n_in,
                              void* d_out, int out_size)
{
    const float* x     = (const float*)d_in[0];
    const int*   eidx  = (const int*)d_in[1];     // int64 in reference -> delivered as int32
    const float* W1    = (const float*)d_in[2];
    const float* b1    = (const float*)d_in[3];
    const float* gamma = (const float*)d_in[4];
    const float* beta  = (const float*)d_in[5];
    const float* W2    = (const float*)d_in[6];
    const float* b2    = (const float*)d_in[7];
    float*       out   = (float*)d_out;

    const int N = in_sizes[0] / D128;          // 50000
    const int E = in_sizes[1] / 2;             // 800000
    const int* src = eidx;
    const int* dst = eidx + E;

    float* H;  cudaGetSymbolAddress((void**)&H,  g_H);
    float* O1; cudaGetSymbolAddress((void**)&O1, g_O1);
    float* scl; cudaGetSymbolAddress((void**)&scl, g_scale);
    float* bia; cudaGetSymbolAddress((void**)&bia, g_bias);

    const int TPB = 256;
    int gridN   = (N + TPB - 1) / TPB;
    int gridE   = (E + TPB - 1) / TPB;
    long long lanes = (long long)E * 32;
    int gridEw  = (int)((lanes + TPB - 1) / TPB);  // warp per edge
    int gridF4  = (N * 32 + TPB - 1) / TPB;        // float4 per thread
    int gridG   = (N + 63) / 64;

    k_init<<<gridN, TPB>>>(N);
    k_deg<<<gridE, TPB>>>(dst, E);
    k_dinv<<<gridN, TPB>>>(N);

    // layer 1
    k_gemm<<<gridG, TPB>>>(x, W1, H, N, nullptr, nullptr);
    k_selfinit<<<gridF4, TPB>>>(H, b1, O1, N);
    k_scatter<<<gridEw, TPB>>>(H, O1, src, dst, E);

    // batchnorm stats
    k_bnreduce<<<256, TPB>>>(O1, N);
    k_bnfinal<<<1, 128>>>(gamma, beta, N);

    // layer 2 (BN affine + ReLU fused into GEMM input load)
    k_gemm<<<gridG, TPB>>>(O1, W2, H, N, scl, bia);
    k_selfinit<<<gridF4, TPB>>>(H, b2, out, N);
    k_scatter<<<gridEw, TPB>>>(H, out, src, dst, E);
}

// round 3
// speedup vs baseline: 1.0962x; 1.0962x over previous
#include <cuda_runtime.h>
#include <cstdint>

#define D128 128
#define MAXN 50000

// ---------------- scratch (no cudaMalloc allowed) ----------------
__device__ float g_H[MAXN * D128];    // GEMM output (gather source for scatter)
__device__ float g_O1[MAXN * D128];   // layer-1 aggregated output
__device__ int   g_deg[MAXN];
__device__ float g_dinv[MAXN];
__device__ float g_sum[D128];
__device__ float g_sumsq[D128];
__device__ float g_scale[D128];
__device__ float g_bias[D128];

// ---------------- init: deg=1 (self loop), zero BN sums ----------------
__global__ void k_init(int N) {
    int i = blockIdx.x * blockDim.x + threadIdx.x;
    if (i < N) g_deg[i] = 1;
    if (i < D128) { g_sum[i] = 0.f; g_sumsq[i] = 0.f; }
}

__global__ void k_deg(const int* __restrict__ dst, int E) {
    int e = blockIdx.x * blockDim.x + threadIdx.x;
    if (e < E) atomicAdd(&g_deg[dst[e]], 1);
}

__global__ void k_dinv(int N) {
    int i = blockIdx.x * blockDim.x + threadIdx.x;
    if (i < N) g_dinv[i] = rsqrtf((float)g_deg[i]);
}

// ---------------- GEMM + fused self-loop epilogue ----------------
// Tile: 64 rows x 128 cols per block, 128 threads, 8x8 per-thread micro-tile.
// Whole W (64KB) cached in dynamic smem; A staged transposed per 8-k chunk.
// Optional fused BN-affine+ReLU on input (scl non-null).
// Writes H[row] = A@W   and   O[row] = bias + H[row]*dinv[row]^2.
#define AS_STRIDE 68   // 64 rows + 4 pad (keeps float4 alignment: 68*4B = 272B, 16B-aligned)

__global__ __launch_bounds__(128) void k_gemm2(
    const float* __restrict__ A, const float* __restrict__ W,
    float* __restrict__ H, float* __restrict__ O,
    const float* __restrict__ bias, int N,
    const float* __restrict__ scl, const float* __restrict__ bia)
{
    extern __shared__ float smem[];
    float* Ws = smem;                       // [128][128] = 16384 floats
    float* As = smem + 128 * 128;           // [8][AS_STRIDE]

    const int tid  = threadIdx.x;
    const int brow = blockIdx.x * 64;
    const int tx   = tid & 15;              // col group: cols tx*8 .. tx*8+7
    const int ty   = tid >> 4;              // row group: rows ty*8 .. ty*8+7

    // ---- load entire W into shared (coalesced float4) ----
    {
        const float4* Wv = (const float4*)W;
        float4* Wsv = (float4*)Ws;
        #pragma unroll
        for (int i = 0; i < 32; i++)
            Wsv[i * 128 + tid] = Wv[i * 128 + tid];
    }

    float acc[8][8];
    #pragma unroll
    for (int r = 0; r < 8; r++)
        #pragma unroll
        for (int c = 0; c < 8; c++) acc[r][c] = 0.f;

    const int lrow = tid >> 1;      // 0..63  (A-stage row)
    const int half = tid & 1;       // which float4 of the 8-k chunk
    const int grow_ld = brow + lrow;
    const bool ld_ok = (grow_ld < N);
    const float4* Arow = (const float4*)(A + (size_t)grow_ld * D128);

    __syncthreads();   // W ready (also covers first As write ordering)

    for (int ks = 0; ks < D128; ks += 8) {
        // ---- stage A[64 rows][8 k] transposed: As[kk][row] ----
        float4 av = make_float4(0.f, 0.f, 0.f, 0.f);
        if (ld_ok) av = Arow[(ks >> 2) + half];
        if (scl != nullptr) {
            int f = ks + half * 4;
            av.x = fmaxf(fmaf(av.x, scl[f + 0], bia[f + 0]), 0.f);
            av.y = fmaxf(fmaf(av.y, scl[f + 1], bia[f + 1]), 0.f);
            av.z = fmaxf(fmaf(av.z, scl[f + 2], bia[f + 2]), 0.f);
            av.w = fmaxf(fmaf(av.w, scl[f + 3], bia[f + 3]), 0.f);
        }
        {
            int kb = half * 4;
            As[(kb + 0) * AS_STRIDE + lrow] = av.x;
            As[(kb + 1) * AS_STRIDE + lrow] = av.y;
            As[(kb + 2) * AS_STRIDE + lrow] = av.z;
            As[(kb + 3) * AS_STRIDE + lrow] = av.w;
        }
        __syncthreads();

        #pragma unroll
        for (int kk = 0; kk < 8; kk++) {
            const float* ap = &As[kk * AS_STRIDE + ty * 8];
            float4 a0 = *(const float4*)(ap);
            float4 a1 = *(const float4*)(ap + 4);
            const float* wp = &Ws[(ks + kk) * D128 + tx * 8];
            float4 w0 = *(const float4*)(wp);
            float4 w1 = *(const float4*)(wp + 4);
            float a[8] = {a0.x, a0.y, a0.z, a0.w, a1.x, a1.y, a1.z, a1.w};
            float w[8] = {w0.x, w0.y, w0.z, w0.w, w1.x, w1.y, w1.z, w1.w};
            #pragma unroll
            for (int r = 0; r < 8; r++)
                #pragma unroll
                for (int c = 0; c < 8; c++)
                    acc[r][c] = fmaf(a[r], w[c], acc[r][c]);
        }
        __syncthreads();
    }

    // ---- epilogue: H = acc,  O = bias + acc * dinv^2 ----
    const float4* Bv = (const float4*)bias;
    float4 bb0 = Bv[tx * 2];
    float4 bb1 = Bv[tx * 2 + 1];

    #pragma unroll
    for (int r = 0; r < 8; r++) {
        int grow = brow + ty * 8 + r;
        if (grow >= N) break;
        float di = g_dinv[grow];
        float wgt = di * di;
        float4 h0 = make_float4(acc[r][0], acc[r][1], acc[r][2], acc[r][3]);
        float4 h1 = make_float4(acc[r][4], acc[r][5], acc[r][6], acc[r][7]);
        float4* Hp = (float4*)(H + (size_t)grow * D128) + tx * 2;
        Hp[0] = h0;
        Hp[1] = h1;
        float4 o0, o1;
        o0.x = fmaf(h0.x, wgt, bb0.x); o0.y = fmaf(h0.y, wgt, bb0.y);
        o0.z = fmaf(h0.z, wgt, bb0.z); o0.w = fmaf(h0.w, wgt, bb0.w);
        o1.x = fmaf(h1.x, wgt, bb1.x); o1.y = fmaf(h1.y, wgt, bb1.y);
        o1.z = fmaf(h1.z, wgt, bb1.z); o1.w = fmaf(h1.w, wgt, bb1.w);
        float4* Op = (float4*)(O + (size_t)grow * D128) + tx * 2;
        Op[0] = o0;
        Op[1] = o1;
    }
}

// ---------------- edge scatter: O[dst] += H[src] * dinv[src]*dinv[dst] ----------------
__device__ __forceinline__ void red_add_v4(float* p, float a, float b, float c, float d) {
    asm volatile("red.global.add.v4.f32 [%0], {%1,%2,%3,%4};"
                 :: "l"(p), "f"(a), "f"(b), "f"(c), "f"(d) : "memory");
}

__global__ __launch_bounds__(256) void k_scatter(
    const float* __restrict__ H, float* __restrict__ O,
    const int* __restrict__ src, const int* __restrict__ dst, int E)
{
    int warp = (blockIdx.x * blockDim.x + threadIdx.x) >> 5;
    int lane = threadIdx.x & 31;
    if (warp >= E) return;
    int s = src[warp];
    int d = dst[warp];
    float nrm = g_dinv[s] * g_dinv[d];
    float4 v = ((const float4*)(H + (size_t)s * D128))[lane];
    float* p = O + (size_t)d * D128 + lane * 4;
    red_add_v4(p, v.x * nrm, v.y * nrm, v.z * nrm, v.w * nrm);
}

// ---------------- BatchNorm reduce ----------------
__global__ __launch_bounds__(256) void k_bnreduce(const float* __restrict__ H, int N) {
    int f    = threadIdx.x & 127;
    int half = threadIdx.x >> 7;
    float s = 0.f, s2 = 0.f;
    for (int row = blockIdx.x * 2 + half; row < N; row += gridDim.x * 2) {
        float v = H[(size_t)row * D128 + f];
        s += v;
        s2 = fmaf(v, v, s2);
    }
    __shared__ float sh[256], sh2[256];
    sh[threadIdx.x] = s; sh2[threadIdx.x] = s2;
    __syncthreads();
    if (threadIdx.x < 128) {
        atomicAdd(&g_sum[f],   sh[f] + sh[f + 128]);
        atomicAdd(&g_sumsq[f], sh2[f] + sh2[f + 128]);
    }
}

__global__ void k_bnfinal(const float* __restrict__ gamma, const float* __restrict__ beta, int N) {
    int f = threadIdx.x;
    if (f >= D128) return;
    float inv_n = 1.0f / (float)N;
    float mu  = g_sum[f] * inv_n;
    float var = g_sumsq[f] * inv_n - mu * mu;
    float rstd = rsqrtf(var + 1e-5f);
    float s = rstd * gamma[f];
    g_scale[f] = s;
    g_bias[f]  = beta[f] - mu * s;
}

// ---------------- launch ----------------
extern "C" void kernel_launch(void* const* d_in, const int* in_sizes, int n_in,
                              void* d_out, int out_size)
{
    const float* x     = (const float*)d_in[0];
    const int*   eidx  = (const int*)d_in[1];
    const float* W1    = (const float*)d_in[2];
    const float* b1    = (const float*)d_in[3];
    const float* gamma = (const float*)d_in[4];
    const float* beta  = (const float*)d_in[5];
    const float* W2    = (const float*)d_in[6];
    const float* b2    = (const float*)d_in[7];
    float*       out   = (float*)d_out;

    const int N = in_sizes[0] / D128;          // 50000
    const int E = in_sizes[1] / 2;             // 800000
    const int* src = eidx;
    const int* dst = eidx + E;

    float* H;  cudaGetSymbolAddress((void**)&H,  g_H);
    float* O1; cudaGetSymbolAddress((void**)&O1, g_O1);
    float* scl; cudaGetSymbolAddress((void**)&scl, g_scale);
    float* bia; cudaGetSymbolAddress((void**)&bia, g_bias);

    const int GEMM_SMEM = (128 * 128 + 8 * AS_STRIDE) * 4;   // ~67.7 KB
    static bool attr_set = false;
    if (!attr_set) {
        cudaFuncSetAttribute(k_gemm2, cudaFuncAttributeMaxDynamicSharedMemorySize, GEMM_SMEM);
        attr_set = true;
    }

    const int TPB = 256;
    int gridN  = (N + TPB - 1) / TPB;
    int gridE  = (E + TPB - 1) / TPB;
    long long lanes = (long long)E * 32;
    int gridEw = (int)((lanes + TPB - 1) / TPB);   // 1 warp per edge
    int gridG  = (N + 63) / 64;

    k_init<<<gridN, TPB>>>(N);
    k_deg<<<gridE, TPB>>>(dst, E);
    k_dinv<<<gridN, TPB>>>(N);

    // layer 1: GEMM + fused self-loop init
    k_gemm2<<<gridG, 128, GEMM_SMEM>>>(x, W1, H, O1, b1, N, nullptr, nullptr);
    k_scatter<<<gridEw, TPB>>>(H, O1, src, dst, E);

    // batchnorm stats -> scale/bias
    k_bnreduce<<<256, TPB>>>(O1, N);
    k_bnfinal<<<1, 128>>>(gamma, beta, N);

    // layer 2: BN+ReLU fused into GEMM input, self-loop fused into epilogue
    k_gemm2<<<gridG, 128, GEMM_SMEM>>>(O1, W2, H, out, b2, N, scl, bia);
    k_scatter<<<gridEw, TPB>>>(H, out, src, dst, E);
}